// round 12
// baseline (speedup 1.0000x reference)
#include <cuda_runtime.h>

// Problem constants
#define BTOT   100000
#define NNB    16
#define NOB    8
#define SDIM   4
#define HID    64
#define DOBS   85
#define DS_C   0.2f
#define GAM_C  0.01f
#define NB_OFF 5
#define OB_OFF 69

typedef unsigned long long ull;
#define ABSM 0x7FFFFFFF7FFFFFFFULL

// ---- packed f32x2 helpers (SASS FFMA2 / packed FADD path) -------------
__device__ __forceinline__ ull pk2(float lo, float hi) {
    ull r; asm("mov.b64 %0,{%1,%2};" : "=l"(r) : "f"(lo), "f"(hi)); return r;
}
__device__ __forceinline__ void up2(ull v, float& lo, float& hi) {
    asm("mov.b64 {%0,%1},%2;" : "=f"(lo), "=f"(hi) : "l"(v));
}
__device__ __forceinline__ ull fma2(ull a, ull b, ull c) {
    ull d; asm("fma.rn.f32x2 %0,%1,%2,%3;" : "=l"(d) : "l"(a), "l"(b), "l"(c)); return d;
}
__device__ __forceinline__ ull add2(ull a, ull b) {
    ull d; asm("add.rn.f32x2 %0,%1,%2;" : "=l"(d) : "l"(a), "l"(b)); return d;
}

__global__ __launch_bounds__(256, 3) void barrier_net_kernel(
    const float* __restrict__ x,
    const float* __restrict__ phi_w1, const float* __restrict__ phi_b1,
    const float* __restrict__ phi_w2, const float* __restrict__ phi_b2,
    const float* __restrict__ obs_w1, const float* __restrict__ obs_b1,
    const float* __restrict__ obs_w2, const float* __restrict__ obs_b2,
    const float* __restrict__ rho_w1, const float* __restrict__ rho_b1,
    const float* __restrict__ rho_w2, const float* __restrict__ rho_b2,
    const float* __restrict__ psi_w1, const float* __restrict__ psi_b1,
    const float* __restrict__ psi_w2, const float* __restrict__ psi_b2,
    float* __restrict__ out)
{
    // w1 layers stored DUPLICATED per hidden unit so one LDS.128 yields two
    // packed (w,w) operands. phi/obs w2 pre-scaled by 0.5 (relu = (h+|h|)/2
    // with the 1/2 folded into w2).
    __shared__ __align__(16) float s_phi_w1d[HID * 8];
    __shared__ __align__(8)  float s_phi_b1d[HID * 2];
    __shared__ __align__(16) float s_phi_w2 [HID * 16];   // ×0.5
    __shared__ __align__(16) float s_obs_w1d[HID * 4];
    __shared__ __align__(8)  float s_obs_b1d[HID * 2];
    __shared__ __align__(16) float s_obs_w2 [HID * 16];   // ×0.5
    __shared__ __align__(16) float s_rho_w1t[HID * 16];   // [j][k]
    __shared__             float s_rho_b1 [HID];
    __shared__ __align__(8)  float s_rho_w2 [HID * 2];
    __shared__ __align__(16) float s_psi_w1t[HID * 4];    // [j][k] = {rho0,rho1,g0,g1}
    __shared__             float s_psi_b1 [HID];
    __shared__ __align__(8)  float s_psi_w2 [HID * 2];
    __shared__ __align__(16) float s_accinit[16];         // NN*phi_b2 + NO*obs_b2
    __shared__             float s_rho_b2 [2];
    __shared__             float s_psi_b2 [2];

    const int tid = threadIdx.x;

    // Cooperative staging (blockDim = 256)
    for (int i = tid; i < HID * 8; i += 256) {
        int j = i >> 3, c = (i >> 1) & 3;
        s_phi_w1d[i] = phi_w1[c * HID + j];
    }
    for (int i = tid; i < HID * 4; i += 256) {
        int j = i >> 2, c = (i >> 1) & 1;
        s_obs_w1d[i] = obs_w1[c * HID + j];
        int j2 = i >> 2, k2 = i & 3;
        s_psi_w1t[i] = psi_w1[k2 * HID + j2];
    }
    for (int i = tid; i < HID * 2; i += 256) {
        int j = i >> 1;
        s_phi_b1d[i] = phi_b1[j];
        s_obs_b1d[i] = obs_b1[j];
        s_rho_w2[i]  = rho_w2[i];
        s_psi_w2[i]  = psi_w2[i];
    }
    for (int i = tid; i < HID * 16; i += 256) {
        int j = i >> 4, k = i & 15;
        s_rho_w1t[i] = rho_w1[k * HID + j];
        s_phi_w2[i]  = 0.5f * phi_w2[i];
        s_obs_w2[i]  = 0.5f * obs_w2[i];
    }
    for (int i = tid; i < HID; i += 256) {
        s_rho_b1[i] = rho_b1[i];
        s_psi_b1[i] = psi_b1[i];
    }
    if (tid < 16) s_accinit[tid] = (float)NNB * phi_b2[tid] + (float)NOB * obs_b2[tid];
    if (tid < 2)  { s_rho_b2[tid] = rho_b2[tid]; s_psi_b2[tid] = psi_b2[tid]; }
    __syncthreads();

    // Lane-pair decomposition: 2 threads per sample.
    // CLAMP (don't return) so the full-mask shfl reduction below is legal.
    const int gthread = blockIdx.x * 256 + tid;
    int s = gthread >> 1;
    const int half = gthread & 1;            // which neighbor/obs half
    const bool writer = (half == 0) && (s < BTOT);
    if (s >= BTOT) s = BTOT - 1;

    const float* xr = x + (long long)s * DOBS;

    // ---- stage THIS HALF's 8 neighbors packed in pairs; partial barrier
    ull pn0[4], pn1[4], pn2[4], pn3[4];
    float bar0 = 0.f, bar1 = 0.f;
    {
        const float* nb = xr + NB_OFF + half * 8 * SDIM;
        #pragma unroll
        for (int p = 0; p < 4; p++) {
            float a0 = __ldg(nb + 8*p + 0), a1 = __ldg(nb + 8*p + 1);
            float a2 = __ldg(nb + 8*p + 2), a3 = __ldg(nb + 8*p + 3);
            float c0 = __ldg(nb + 8*p + 4), c1 = __ldg(nb + 8*p + 5);
            float c2 = __ldg(nb + 8*p + 6), c3 = __ldg(nb + 8*p + 7);

            float na = sqrtf(fmaf(a0, a0, a1 * a1));
            float ka = __fdividef(GAM_C, na - DS_C);
            bar0 -= ka * a0;  bar1 -= ka * a1;
            float nc = sqrtf(fmaf(c0, c0, c1 * c1));
            float kc = __fdividef(GAM_C, nc - DS_C);
            bar0 -= kc * c0;  bar1 -= kc * c1;

            pn0[p] = pk2(a0, c0);
            pn1[p] = pk2(a1, c1);
            pn2[p] = pk2(a2, c2);
            pn3[p] = pk2(a3, c3);
        }
    }

    // Partial acc: bias init carried by half 0 only (added once per sample).
    ull accp[8];
    {
        const ull* ai = (const ull*)s_accinit;
        #pragma unroll
        for (int t = 0; t < 8; t++) accp[t] = half ? 0ull : ai[t];
    }

    // ---- phi: j outer; this half's 8 neighbors (4 packed pairs) -------
    {
        const ulonglong2* w1d = (const ulonglong2*)s_phi_w1d;
        const ull*        bdp = (const ull*)s_phi_b1d;
        const ulonglong2* w2p = (const ulonglong2*)s_phi_w2;
        #pragma unroll 2
        for (int j = 0; j < HID; j++) {
            ulonglong2 wa = w1d[2 * j + 0];   // (wx,wx),(wy,wy)
            ulonglong2 wb = w1d[2 * j + 1];   // (wz,wz),(ww,ww)
            ull bb = bdp[j];
            ull sh = 0ull, sa = 0ull;         // packed Σh, Σ|h|
            #pragma unroll
            for (int p = 0; p < 4; p++) {
                ull h = fma2(pn0[p], wa.x, bb);
                h = fma2(pn1[p], wa.y, h);
                h = fma2(pn2[p], wb.x, h);
                h = fma2(pn3[p], wb.y, h);
                sh = add2(sh, h);
                sa = add2(sa, h & ABSM);
            }
            ull s2 = add2(sh, sa);            // packed Σ(h+|h|) = 2Σrelu
            float sx, sy; up2(s2, sx, sy);
            float hsum = sx + sy;
            ull hd = pk2(hsum, hsum);
            #pragma unroll
            for (int q = 0; q < 4; q++) {
                ulonglong2 v = w2p[j * 4 + q];   // pre-scaled ×0.5
                accp[2 * q + 0] = fma2(hd, v.x, accp[2 * q + 0]);
                accp[2 * q + 1] = fma2(hd, v.y, accp[2 * q + 1]);
            }
        }
    }

    // ---- obs: this half's 4 observations (2 packed pairs) -------------
    {
        ull pm0[2], pm1[2];
        const float* oa = xr + OB_OFF + half * 8;
        #pragma unroll
        for (int p = 0; p < 2; p++) {
            pm0[p] = pk2(__ldg(oa + 4*p + 0), __ldg(oa + 4*p + 2));
            pm1[p] = pk2(__ldg(oa + 4*p + 1), __ldg(oa + 4*p + 3));
        }
        const ulonglong2* ow1 = (const ulonglong2*)s_obs_w1d;
        const ull*        obd = (const ull*)s_obs_b1d;
        const ulonglong2* ow2 = (const ulonglong2*)s_obs_w2;
        #pragma unroll 4
        for (int j = 0; j < HID; j++) {
            ulonglong2 w = ow1[j];
            ull bb = obd[j];
            ull h0 = fma2(pm0[0], w.x, bb);
            h0 = fma2(pm1[0], w.y, h0);
            ull h1 = fma2(pm0[1], w.x, bb);
            h1 = fma2(pm1[1], w.y, h1);
            ull s2 = add2(add2(h0, h0 & ABSM), add2(h1, h1 & ABSM));
            float sx, sy; up2(s2, sx, sy);
            float hsum = sx + sy;
            ull hd = pk2(hsum, hsum);
            #pragma unroll
            for (int q = 0; q < 4; q++) {
                ulonglong2 v = ow2[j * 4 + q];   // pre-scaled ×0.5
                accp[2 * q + 0] = fma2(hd, v.x, accp[2 * q + 0]);
                accp[2 * q + 1] = fma2(hd, v.y, accp[2 * q + 1]);
            }
        }
    }

    // ---- combine the lane pair: acc + barrier -------------------------
    #pragma unroll
    for (int t = 0; t < 8; t++)
        accp[t] = add2(accp[t], __shfl_xor_sync(0xFFFFFFFFu, accp[t], 1));
    bar0 += __shfl_xor_sync(0xFFFFFFFFu, bar0, 1);
    bar1 += __shfl_xor_sync(0xFFFFFFFFu, bar1, 1);

    // ---- rho: 16 -> 64 -> 2 (both lanes redundant — lockstep, free) ---
    float r0 = s_rho_b2[0], r1 = s_rho_b2[1];
    {
        const ulonglong2* rw = (const ulonglong2*)s_rho_w1t;
        #pragma unroll 4
        for (int j = 0; j < HID; j++) {
            ulonglong2 v0 = rw[4 * j + 0], v1 = rw[4 * j + 1];
            ulonglong2 v2 = rw[4 * j + 2], v3 = rw[4 * j + 3];
            ull hp = fma2(accp[0], v0.x, 0ull);
            ull hq = fma2(accp[1], v0.y, 0ull);
            hp = fma2(accp[2], v1.x, hp);
            hq = fma2(accp[3], v1.y, hq);
            hp = fma2(accp[4], v2.x, hp);
            hq = fma2(accp[5], v2.y, hq);
            hp = fma2(accp[6], v3.x, hp);
            hq = fma2(accp[7], v3.y, hq);
            hp = add2(hp, hq);
            float hx, hy; up2(hp, hx, hy);
            float h = fmaxf(hx + hy + s_rho_b1[j], 0.f);
            r0 = fmaf(h, s_rho_w2[2 * j + 0], r0);
            r1 = fmaf(h, s_rho_w2[2 * j + 1], r1);
        }
    }

    // ---- psi: [rho0,rho1,g0,g1] -> 64 -> 2 ----------------------------
    float e0 = s_psi_b2[0], e1 = s_psi_b2[1];
    {
        float g0 = __ldg(xr + 0), g1 = __ldg(xr + 1);
        ull rg0 = pk2(r0, r1);
        ull rg1 = pk2(g0, g1);
        const ulonglong2* pw = (const ulonglong2*)s_psi_w1t;
        #pragma unroll 4
        for (int j = 0; j < HID; j++) {
            ulonglong2 w = pw[j];   // (wx,wy),(wz,ww)
            ull hp = fma2(rg0, w.x, 0ull);
            hp = fma2(rg1, w.y, hp);
            float hx, hy; up2(hp, hx, hy);
            float h = fmaxf(hx + hy + s_psi_b1[j], 0.f);
            e0 = fmaf(h, s_psi_w2[2 * j + 0], e0);
            e1 = fmaf(h, s_psi_w2[2 * j + 1], e1);
        }
    }

    // empty affine == tanh(e); final affine == 2*action
    float a0 = tanhf(tanhf(e0) + bar0);
    float a1 = tanhf(tanhf(e1) + bar1);
    if (writer)
        ((float2*)out)[s] = make_float2(2.f * a0, 2.f * a1);
}

extern "C" void kernel_launch(void* const* d_in, const int* in_sizes, int n_in,
                              void* d_out, int out_size)
{
    const float* x       = (const float*)d_in[0];
    const float* phi_w1  = (const float*)d_in[1];
    const float* phi_b1  = (const float*)d_in[2];
    const float* phi_w2  = (const float*)d_in[3];
    const float* phi_b2  = (const float*)d_in[4];
    const float* obs_w1  = (const float*)d_in[5];
    const float* obs_b1  = (const float*)d_in[6];
    const float* obs_w2  = (const float*)d_in[7];
    const float* obs_b2  = (const float*)d_in[8];
    const float* rho_w1  = (const float*)d_in[9];
    const float* rho_b1  = (const float*)d_in[10];
    const float* rho_w2  = (const float*)d_in[11];
    const float* rho_b2  = (const float*)d_in[12];
    const float* psi_w1  = (const float*)d_in[13];
    const float* psi_b1  = (const float*)d_in[14];
    const float* psi_w2  = (const float*)d_in[15];
    const float* psi_b2  = (const float*)d_in[16];
    float* out = (float*)d_out;

    const int grid = (2 * BTOT + 255) / 256;   // 782 (2 threads per sample)
    barrier_net_kernel<<<grid, 256>>>(
        x,
        phi_w1, phi_b1, phi_w2, phi_b2,
        obs_w1, obs_b1, obs_w2, obs_b2,
        rho_w1, rho_b1, rho_w2, rho_b2,
        psi_w1, psi_b1, psi_w2, psi_b2,
        out);
}

// round 13
// speedup vs baseline: 1.3690x; 1.3690x over previous
#include <cuda_runtime.h>

// Problem constants
#define BTOT   100000
#define NNB    16
#define NOB    8
#define SDIM   4
#define HID    64
#define DOBS   85
#define DS_C   0.2f
#define GAM_C  0.01f
#define NB_OFF 5
#define OB_OFF 69

typedef unsigned long long ull;

// ---- packed f32x2 helpers (SASS FFMA2 path) ---------------------------
__device__ __forceinline__ ull pk2(float lo, float hi) {
    ull r; asm("mov.b64 %0,{%1,%2};" : "=l"(r) : "f"(lo), "f"(hi)); return r;
}
__device__ __forceinline__ void up2(ull v, float& lo, float& hi) {
    asm("mov.b64 {%0,%1},%2;" : "=f"(lo), "=f"(hi) : "l"(v));
}
__device__ __forceinline__ ull fma2(ull a, ull b, ull c) {
    ull d; asm("fma.rn.f32x2 %0,%1,%2,%3;" : "=l"(d) : "l"(a), "l"(b), "l"(c)); return d;
}

__global__ __launch_bounds__(256, 2) void barrier_net_kernel(
    const float* __restrict__ x,
    const float* __restrict__ phi_w1, const float* __restrict__ phi_b1,
    const float* __restrict__ phi_w2, const float* __restrict__ phi_b2,
    const float* __restrict__ obs_w1, const float* __restrict__ obs_b1,
    const float* __restrict__ obs_w2, const float* __restrict__ obs_b2,
    const float* __restrict__ rho_w1, const float* __restrict__ rho_b1,
    const float* __restrict__ rho_w2, const float* __restrict__ rho_b2,
    const float* __restrict__ psi_w1, const float* __restrict__ psi_b1,
    const float* __restrict__ psi_w2, const float* __restrict__ psi_b2,
    float* __restrict__ out)
{
    // Dynamic smem: this block's 256 x-rows (256*85 floats = 87040 B),
    // loaded COALESCED (float4) instead of 74 scattered per-thread LDGs.
    // Row stride 85 floats: gcd(85,32)=1 => per-thread row reads are
    // bank-conflict-free.
    extern __shared__ float s_x[];

    // Static smem: weight staging. w1 layers DUPLICATED per hidden unit so
    // one LDS.128 yields two packed (w,w) operands.
    __shared__ __align__(16) float s_phi_w1d[HID * 8];
    __shared__ __align__(8)  float s_phi_b1d[HID * 2];
    __shared__ __align__(16) float s_phi_w2 [HID * 16];
    __shared__ __align__(16) float s_obs_w1d[HID * 4];
    __shared__ __align__(8)  float s_obs_b1d[HID * 2];
    __shared__ __align__(16) float s_obs_w2 [HID * 16];
    __shared__ __align__(16) float s_rho_w1t[HID * 16];   // [j][k]
    __shared__             float s_rho_b1 [HID];
    __shared__ __align__(8)  float s_rho_w2 [HID * 2];
    __shared__ __align__(16) float s_psi_w1t[HID * 4];    // [j][k]={rho0,rho1,g0,g1}
    __shared__             float s_psi_b1 [HID];
    __shared__ __align__(8)  float s_psi_w2 [HID * 2];
    __shared__ __align__(16) float s_accinit[16];         // NN*phi_b2 + NO*obs_b2
    __shared__             float s_rho_b2 [2];
    __shared__             float s_psi_b2 [2];

    const int tid = threadIdx.x;

    // ---- coalesced x staging: gmem -> smem (float4) -------------------
    {
        const int base = blockIdx.x * 256;                // always < BTOT
        const int nrows = min(256, BTOT - base);
        const int nf4 = nrows * DOBS / 4;                 // 85*nrows % 4 == 0
        const float4* src = (const float4*)(x + (long long)base * DOBS);
        float4* dst = (float4*)s_x;
        for (int i = tid; i < nf4; i += 256) dst[i] = src[i];
    }

    // ---- weight staging ----------------------------------------------
    for (int i = tid; i < HID * 8; i += 256) {
        int j = i >> 3, c = (i >> 1) & 3;
        s_phi_w1d[i] = phi_w1[c * HID + j];
    }
    for (int i = tid; i < HID * 4; i += 256) {
        int j = i >> 2, c = (i >> 1) & 1;
        s_obs_w1d[i] = obs_w1[c * HID + j];
        int j2 = i >> 2, k2 = i & 3;
        s_psi_w1t[i] = psi_w1[k2 * HID + j2];
    }
    for (int i = tid; i < HID * 2; i += 256) {
        int j = i >> 1;
        s_phi_b1d[i] = phi_b1[j];
        s_obs_b1d[i] = obs_b1[j];
        s_rho_w2[i]  = rho_w2[i];
        s_psi_w2[i]  = psi_w2[i];
    }
    for (int i = tid; i < HID * 16; i += 256) {
        int j = i >> 4, k = i & 15;
        s_rho_w1t[i] = rho_w1[k * HID + j];
        s_phi_w2[i]  = phi_w2[i];
        s_obs_w2[i]  = obs_w2[i];
    }
    for (int i = tid; i < HID; i += 256) {
        s_rho_b1[i] = rho_b1[i];
        s_psi_b1[i] = psi_b1[i];
    }
    if (tid < 16) s_accinit[tid] = (float)NNB * phi_b2[tid] + (float)NOB * obs_b2[tid];
    if (tid < 2)  { s_rho_b2[tid] = rho_b2[tid]; s_psi_b2[tid] = psi_b2[tid]; }
    __syncthreads();

    const int idx = blockIdx.x * 256 + tid;
    if (idx >= BTOT) return;   // after the sync; no further block syncs

    const float* xr = s_x + tid * DOBS;   // conflict-free smem row

    // ---- stage neighbors packed in pairs; barrier on the fly ----------
    ull pn0[8], pn1[8], pn2[8], pn3[8];
    float bar0 = 0.f, bar1 = 0.f;
    #pragma unroll
    for (int p = 0; p < 8; p++) {
        const float* sp = xr + NB_OFF + (2 * p) * SDIM;
        float a0 = sp[0], a1 = sp[1], a2 = sp[2], a3 = sp[3];
        float c0 = sp[4], c1 = sp[5], c2 = sp[6], c3 = sp[7];

        float na = sqrtf(fmaf(a0, a0, a1 * a1));
        float ka = GAM_C / (na - DS_C);
        bar0 -= ka * a0;  bar1 -= ka * a1;
        float nc = sqrtf(fmaf(c0, c0, c1 * c1));
        float kc = GAM_C / (nc - DS_C);
        bar0 -= kc * c0;  bar1 -= kc * c1;

        pn0[p] = pk2(a0, c0);
        pn1[p] = pk2(a1, c1);
        pn2[p] = pk2(a2, c2);
        pn3[p] = pk2(a3, c3);
    }
    ull pm0[4], pm1[4];
    #pragma unroll
    for (int p = 0; p < 4; p++) {
        const float* oa = xr + OB_OFF + 4 * p;
        pm0[p] = pk2(oa[0], oa[2]);
        pm1[p] = pk2(oa[1], oa[3]);
    }
    float g0 = xr[0], g1 = xr[1];

    // acc packed: accp[t] = (acc_{2t}, acc_{2t+1}); output biases pre-folded
    ull accp[8];
    {
        const ull* ai = (const ull*)s_accinit;
        #pragma unroll
        for (int t = 0; t < 8; t++) accp[t] = ai[t];
    }

    // ---- phi: j outer; 2 neighbors per FFMA2 --------------------------
    {
        const ulonglong2* w1d = (const ulonglong2*)s_phi_w1d;
        const ull*        bdp = (const ull*)s_phi_b1d;
        const ulonglong2* w2p = (const ulonglong2*)s_phi_w2;
        #pragma unroll 2
        for (int j = 0; j < HID; j++) {
            ulonglong2 wa = w1d[2 * j + 0];   // (wx,wx),(wy,wy)
            ulonglong2 wb = w1d[2 * j + 1];   // (wz,wz),(ww,ww)
            ull bb = bdp[j];
            float hsA = 0.f, hsB = 0.f;
            #pragma unroll
            for (int p = 0; p < 8; p++) {
                ull h = fma2(pn0[p], wa.x, bb);
                h = fma2(pn1[p], wa.y, h);
                h = fma2(pn2[p], wb.x, h);
                h = fma2(pn3[p], wb.y, h);
                float hx, hy; up2(h, hx, hy);
                hsA += fmaxf(hx, 0.f);
                hsB += fmaxf(hy, 0.f);
            }
            float hsum = hsA + hsB;
            ull hd = pk2(hsum, hsum);
            #pragma unroll
            for (int q = 0; q < 4; q++) {
                ulonglong2 v = w2p[j * 4 + q];
                accp[2 * q + 0] = fma2(hd, v.x, accp[2 * q + 0]);
                accp[2 * q + 1] = fma2(hd, v.y, accp[2 * q + 1]);
            }
        }
    }

    // ---- obs: j outer --------------------------------------------------
    {
        const ulonglong2* ow1 = (const ulonglong2*)s_obs_w1d;
        const ull*        obd = (const ull*)s_obs_b1d;
        const ulonglong2* ow2 = (const ulonglong2*)s_obs_w2;
        #pragma unroll 2
        for (int j = 0; j < HID; j++) {
            ulonglong2 w = ow1[j];
            ull bb = obd[j];
            float hsA = 0.f, hsB = 0.f;
            #pragma unroll
            for (int p = 0; p < 4; p++) {
                ull h = fma2(pm0[p], w.x, bb);
                h = fma2(pm1[p], w.y, h);
                float hx, hy; up2(h, hx, hy);
                hsA += fmaxf(hx, 0.f);
                hsB += fmaxf(hy, 0.f);
            }
            float hsum = hsA + hsB;
            ull hd = pk2(hsum, hsum);
            #pragma unroll
            for (int q = 0; q < 4; q++) {
                ulonglong2 v = ow2[j * 4 + q];
                accp[2 * q + 0] = fma2(hd, v.x, accp[2 * q + 0]);
                accp[2 * q + 1] = fma2(hd, v.y, accp[2 * q + 1]);
            }
        }
    }

    // ---- rho: 16 -> 64 -> 2 (packed 16-dot) ---------------------------
    float r0 = s_rho_b2[0], r1 = s_rho_b2[1];
    {
        const ulonglong2* rw = (const ulonglong2*)s_rho_w1t;
        #pragma unroll 2
        for (int j = 0; j < HID; j++) {
            ulonglong2 v0 = rw[4 * j + 0], v1 = rw[4 * j + 1];
            ulonglong2 v2 = rw[4 * j + 2], v3 = rw[4 * j + 3];
            ull hp = fma2(accp[0], v0.x, 0ull);
            hp = fma2(accp[1], v0.y, hp);
            hp = fma2(accp[2], v1.x, hp);
            hp = fma2(accp[3], v1.y, hp);
            hp = fma2(accp[4], v2.x, hp);
            hp = fma2(accp[5], v2.y, hp);
            hp = fma2(accp[6], v3.x, hp);
            hp = fma2(accp[7], v3.y, hp);
            float hx, hy; up2(hp, hx, hy);
            float h = fmaxf(hx + hy + s_rho_b1[j], 0.f);
            r0 = fmaf(h, s_rho_w2[2 * j + 0], r0);
            r1 = fmaf(h, s_rho_w2[2 * j + 1], r1);
        }
    }

    // ---- psi: [rho0,rho1,g0,g1] -> 64 -> 2 ----------------------------
    float e0 = s_psi_b2[0], e1 = s_psi_b2[1];
    {
        ull rg0 = pk2(r0, r1);
        ull rg1 = pk2(g0, g1);
        const ulonglong2* pw = (const ulonglong2*)s_psi_w1t;
        #pragma unroll 4
        for (int j = 0; j < HID; j++) {
            ulonglong2 w = pw[j];   // (wx,wy),(wz,ww)
            ull hp = fma2(rg0, w.x, 0ull);
            hp = fma2(rg1, w.y, hp);
            float hx, hy; up2(hp, hx, hy);
            float h = fmaxf(hx + hy + s_psi_b1[j], 0.f);
            e0 = fmaf(h, s_psi_w2[2 * j + 0], e0);
            e1 = fmaf(h, s_psi_w2[2 * j + 1], e1);
        }
    }

    // empty affine == tanh(e); final affine == 2*action
    float a0 = tanhf(tanhf(e0) + bar0);
    float a1 = tanhf(tanhf(e1) + bar1);
    ((float2*)out)[idx] = make_float2(2.f * a0, 2.f * a1);
}

extern "C" void kernel_launch(void* const* d_in, const int* in_sizes, int n_in,
                              void* d_out, int out_size)
{
    const float* x       = (const float*)d_in[0];
    const float* phi_w1  = (const float*)d_in[1];
    const float* phi_b1  = (const float*)d_in[2];
    const float* phi_w2  = (const float*)d_in[3];
    const float* phi_b2  = (const float*)d_in[4];
    const float* obs_w1  = (const float*)d_in[5];
    const float* obs_b1  = (const float*)d_in[6];
    const float* obs_w2  = (const float*)d_in[7];
    const float* obs_b2  = (const float*)d_in[8];
    const float* rho_w1  = (const float*)d_in[9];
    const float* rho_b1  = (const float*)d_in[10];
    const float* rho_w2  = (const float*)d_in[11];
    const float* rho_b2  = (const float*)d_in[12];
    const float* psi_w1  = (const float*)d_in[13];
    const float* psi_b1  = (const float*)d_in[14];
    const float* psi_w2  = (const float*)d_in[15];
    const float* psi_b2  = (const float*)d_in[16];
    float* out = (float*)d_out;

    const int dyn_smem = 256 * DOBS * sizeof(float);   // 87040 B
    static bool attr_done = false;
    if (!attr_done) {
        cudaFuncSetAttribute(barrier_net_kernel,
                             cudaFuncAttributeMaxDynamicSharedMemorySize, dyn_smem);
        attr_done = true;
    }

    const int grid = (BTOT + 255) / 256;   // 391
    barrier_net_kernel<<<grid, 256, dyn_smem>>>(
        x,
        phi_w1, phi_b1, phi_w2, phi_b2,
        obs_w1, obs_b1, obs_w2, obs_b2,
        rho_w1, rho_b1, rho_w2, rho_b2,
        psi_w1, psi_b1, psi_w2, psi_b2,
        out);
}